// round 16
// baseline (speedup 1.0000x reference)
#include <cuda_runtime.h>
#include <cuda_bf16.h>
#include <cstdint>

// Problem constants (fixed by setup_inputs)
#define BB 8
#define TT 512
#define DD 768
#define LL 16
#define LD 128
#define OO 4096          // LABEL_DIM * N_LABELS * 2
#define NTOK 4096        // B*T
#define BN_EPS 1e-5f
#define SCORE_ELEMS ((size_t)BB * LL * TT * TT)   // 33554432

// ---------------- scratch (device globals: sanctioned, no runtime alloc) ----
__device__ float g_sums[2 * DD];          // [0..768) sum, [768..1536) sumsq
__device__ float g_scale[DD];
__device__ float g_shift[DD];
__device__ float g_mask[NTOK];            // normalized mask as 0/1 float
__device__ float g_start[(size_t)BB * LL * TT * LD];  // 32 MB
__device__ float g_end  [(size_t)BB * LL * TT * LD];  // 32 MB

// ---------------- helpers ----------------
__device__ __forceinline__ uint32_t f2tf(float x) {
    uint32_t r;
    asm("cvt.rna.tf32.f32 %0, %1;" : "=r"(r) : "f"(x));
    return r;
}

__device__ __forceinline__ void mma_tf32(float* c, const uint32_t* a, const uint32_t* b) {
    asm volatile(
        "mma.sync.aligned.m16n8k8.row.col.f32.tf32.tf32.f32 "
        "{%0,%1,%2,%3},{%4,%5,%6,%7},{%8,%9},{%0,%1,%2,%3};"
        : "+f"(c[0]), "+f"(c[1]), "+f"(c[2]), "+f"(c[3])
        : "r"(a[0]), "r"(a[1]), "r"(a[2]), "r"(a[3]), "r"(b[0]), "r"(b[1]));
}

// ---------------- kernel 0: mask dtype detect + normalize + zero stats -------
// Single block. Inspects the first 4KB of the raw mask buffer (safe under all
// candidate dtypes: bool(1B)=4KB total, int32/float32=16KB total) to decide
// the element width, then fills g_mask[4096] with 0/1 floats.
__global__ void maskprep_kernel(const void* __restrict__ mask_raw) {
    __shared__ int s_flags[2];  // [0]=word01_viol, [1]=wordfloat_viol
    __shared__ int s_hasfloat1;
    __shared__ int s_mode;      // 0=bool(1B) 1=int32 2=float32
    int tid = threadIdx.x;      // 256 threads
    if (tid == 0) { s_flags[0] = 0; s_flags[1] = 0; s_hasfloat1 = 0; }
    __syncthreads();

    const uint32_t* w = (const uint32_t*)mask_raw;
    int v01 = 0, vfl = 0, hf = 0;
    for (int i = tid; i < 1024; i += 256) {     // first 4KB only
        uint32_t x = w[i];
        if (x > 1u) v01 = 1;
        if (x != 0u && x != 0x3F800000u) vfl = 1;
        if (x == 0x3F800000u) hf = 1;
    }
    if (v01) atomicOr(&s_flags[0], 1);
    if (vfl) atomicOr(&s_flags[1], 1);
    if (hf) atomicOr(&s_hasfloat1, 1);
    __syncthreads();
    if (tid == 0) {
        if (!s_flags[1] && s_hasfloat1) s_mode = 2;       // float32 0/1 pattern
        else if (!s_flags[0]) s_mode = 1;                 // int32 0/1 pattern
        else s_mode = 0;                                  // byte bool
    }
    __syncthreads();
    int mode = s_mode;

    for (int i = tid; i < NTOK; i += 256) {
        float m;
        if (mode == 0) {
            m = ((const unsigned char*)mask_raw)[i] ? 1.f : 0.f;
        } else if (mode == 1) {
            m = ((const int*)mask_raw)[i] ? 1.f : 0.f;
        } else {
            m = (((const float*)mask_raw)[i] != 0.f) ? 1.f : 0.f;
        }
        g_mask[i] = m;
    }
    for (int i = tid; i < 2 * DD; i += 256) g_sums[i] = 0.f;
}

// ---------------- kernel 1: masked BN partial sums ----------------
__global__ void stats_kernel(const float* __restrict__ feat) {
    int tid = threadIdx.x;
    int row0 = blockIdx.x * 32;
    float s[3] = {0.f, 0.f, 0.f}, q[3] = {0.f, 0.f, 0.f};
    for (int r = 0; r < 32; r++) {
        int row = row0 + r;
        if (g_mask[row] != 0.f) {
            const float* p = feat + (size_t)row * DD;
#pragma unroll
            for (int j = 0; j < 3; j++) {
                float x = p[tid + j * 256];
                s[j] += x;
                q[j] += x * x;
            }
        }
    }
#pragma unroll
    for (int j = 0; j < 3; j++) {
        atomicAdd(&g_sums[tid + j * 256], s[j]);
        atomicAdd(&g_sums[DD + tid + j * 256], q[j]);
    }
}

// ---------------- kernel 2: finalize -> scale/shift ----------------
__global__ void finalize_kernel(const float* __restrict__ gamma,
                                const float* __restrict__ beta) {
    __shared__ float ccnt;
    int tid = threadIdx.x;  // 256
    if (tid == 0) ccnt = 0.f;
    __syncthreads();
    float c = 0.f;
    for (int i = tid; i < NTOK; i += 256) c += g_mask[i];
#pragma unroll
    for (int off = 16; off; off >>= 1) c += __shfl_down_sync(0xffffffffu, c, off);
    if ((tid & 31) == 0) atomicAdd(&ccnt, c);
    __syncthreads();
    float denom = fmaxf(ccnt, 1.f);
    for (int d = tid; d < DD; d += 256) {
        float mean = g_sums[d] / denom;
        float var = g_sums[DD + d] / denom - mean * mean;
        var = fmaxf(var, 0.f);
        float rstd = rsqrtf(var + BN_EPS);
        float sc = rstd * gamma[d];
        g_scale[d] = sc;
        g_shift[d] = beta[d] - mean * sc;
    }
}

// ---------------- kernel 3: GEMM1  h = relu(feats @ W^T + b) ----------------
// feats[t,k] = (x[t,k]*scale[k]+shift[k]) * mask[t]  (fused in A load)
// C tile 128x128, K-step 32, 8 warps (2m x 4n), warp tile 64x32, tf32 MMA.
// Epilogue permutes o=(l,d2,p) into g_start / g_end at [((b*16+l)*512+s)*128+d2].
__global__ __launch_bounds__(256, 2)
void gemm1_kernel(const float* __restrict__ feat,
                  const float* __restrict__ ffw,
                  const float* __restrict__ ffb) {
    __shared__ uint32_t As[128][36];
    __shared__ uint32_t Bs[128][36];

    int tid = threadIdx.x;
    int m0 = blockIdx.y * 128, n0 = blockIdx.x * 128;
    int warp = tid >> 5, lane = tid & 31;
    int wm = warp >> 2, wn = warp & 3;
    int grp = lane >> 2, tig = lane & 3;

    float acc[4][4][4];
#pragma unroll
    for (int i = 0; i < 4; i++)
#pragma unroll
        for (int j = 0; j < 4; j++)
#pragma unroll
            for (int k = 0; k < 4; k++) acc[i][j][k] = 0.f;

    int ldRow = tid >> 3;        // 0..31
    int ldK = (tid & 7) * 4;     // 0,4,...,28

    for (int k0 = 0; k0 < DD; k0 += 32) {
        float4 sc = *(const float4*)(g_scale + k0 + ldK);
        float4 sh = *(const float4*)(g_shift + k0 + ldK);
#pragma unroll
        for (int p = 0; p < 4; p++) {
            int r = ldRow + p * 32;
            // A: normalized features
            int rg = m0 + r;
            float4 x = *(const float4*)(feat + (size_t)rg * DD + k0 + ldK);
            float mrow = g_mask[rg];
            uint4 av;
            av.x = f2tf(fmaf(x.x, sc.x, sh.x) * mrow);
            av.y = f2tf(fmaf(x.y, sc.y, sh.y) * mrow);
            av.z = f2tf(fmaf(x.z, sc.z, sh.z) * mrow);
            av.w = f2tf(fmaf(x.w, sc.w, sh.w) * mrow);
            *(uint4*)&As[r][ldK] = av;
            // B: weight rows
            int ng = n0 + r;
            float4 w = *(const float4*)(ffw + (size_t)ng * DD + k0 + ldK);
            uint4 bv;
            bv.x = f2tf(w.x); bv.y = f2tf(w.y); bv.z = f2tf(w.z); bv.w = f2tf(w.w);
            *(uint4*)&Bs[r][ldK] = bv;
        }
        __syncthreads();

#pragma unroll
        for (int kk = 0; kk < 4; kk++) {
            int ks = kk * 8;
            uint32_t a[4][4], b[4][2];
#pragma unroll
            for (int mi = 0; mi < 4; mi++) {
                int r = wm * 64 + mi * 16;
                a[mi][0] = As[r + grp][ks + tig];
                a[mi][1] = As[r + grp + 8][ks + tig];
                a[mi][2] = As[r + grp][ks + tig + 4];
                a[mi][3] = As[r + grp + 8][ks + tig + 4];
            }
#pragma unroll
            for (int ni = 0; ni < 4; ni++) {
                int cc = wn * 32 + ni * 8 + grp;
                b[ni][0] = Bs[cc][ks + tig];
                b[ni][1] = Bs[cc][ks + tig + 4];
            }
#pragma unroll
            for (int mi = 0; mi < 4; mi++)
#pragma unroll
                for (int ni = 0; ni < 4; ni++) mma_tf32(acc[mi][ni], a[mi], b[ni]);
        }
        __syncthreads();
    }

    // epilogue: bias + relu + permute into start/end
#pragma unroll
    for (int ni = 0; ni < 4; ni++) {
        int col = n0 + wn * 32 + ni * 8 + tig * 2;  // even
        float b0 = __ldg(ffb + col), b1 = __ldg(ffb + col + 1);
        int l = col >> 8;
        int d2 = (col & 255) >> 1;
#pragma unroll
        for (int mi = 0; mi < 4; mi++) {
#pragma unroll
            for (int h = 0; h < 2; h++) {
                int row = m0 + wm * 64 + mi * 16 + grp + h * 8;  // token t
                float h0 = fmaxf(acc[mi][ni][h * 2 + 0] + b0, 0.f);
                float h1 = fmaxf(acc[mi][ni][h * 2 + 1] + b1, 0.f);
                int bb = row >> 9, s = row & 511;
                size_t idx = ((size_t)((bb * LL + l) * TT + s)) * LD + d2;
                g_start[idx] = h0;
                g_end[idx] = h1;
            }
        }
    }
}

// ---------------- kernel 4: GEMM2  scores = S @ E^T + label_bias; + mask ----
// grid (4 n-tiles, 4 m-tiles, 128 bl); K=128 in 4 chunks of 32.
__global__ __launch_bounds__(256, 2)
void gemm2_kernel(const float* __restrict__ lbias,
                  float* __restrict__ out,
                  size_t maskoff,
                  int write_mask) {
    __shared__ uint32_t As[128][36];
    __shared__ uint32_t Bs[128][36];

    int tid = threadIdx.x;
    int bl = blockIdx.z;
    int b = bl >> 4, l = bl & 15;
    int m0 = blockIdx.y * 128, n0 = blockIdx.x * 128;
    int warp = tid >> 5, lane = tid & 31;
    int wm = warp >> 2, wn = warp & 3;
    int grp = lane >> 2, tig = lane & 3;

    const float* S = g_start + (size_t)bl * TT * LD;
    const float* E = g_end + (size_t)bl * TT * LD;

    float acc[4][4][4];
#pragma unroll
    for (int i = 0; i < 4; i++)
#pragma unroll
        for (int j = 0; j < 4; j++)
#pragma unroll
            for (int k = 0; k < 4; k++) acc[i][j][k] = 0.f;

    int ldRow = tid >> 3;
    int ldK = (tid & 7) * 4;

    for (int k0 = 0; k0 < LD; k0 += 32) {
#pragma unroll
        for (int p = 0; p < 4; p++) {
            int r = ldRow + p * 32;
            float4 x = *(const float4*)(S + (size_t)(m0 + r) * LD + k0 + ldK);
            uint4 av;
            av.x = f2tf(x.x); av.y = f2tf(x.y); av.z = f2tf(x.z); av.w = f2tf(x.w);
            *(uint4*)&As[r][ldK] = av;
            float4 w = *(const float4*)(E + (size_t)(n0 + r) * LD + k0 + ldK);
            uint4 bv;
            bv.x = f2tf(w.x); bv.y = f2tf(w.y); bv.z = f2tf(w.z); bv.w = f2tf(w.w);
            *(uint4*)&Bs[r][ldK] = bv;
        }
        __syncthreads();

#pragma unroll
        for (int kk = 0; kk < 4; kk++) {
            int ks = kk * 8;
            uint32_t a[4][4], bf[4][2];
#pragma unroll
            for (int mi = 0; mi < 4; mi++) {
                int r = wm * 64 + mi * 16;
                a[mi][0] = As[r + grp][ks + tig];
                a[mi][1] = As[r + grp + 8][ks + tig];
                a[mi][2] = As[r + grp][ks + tig + 4];
                a[mi][3] = As[r + grp + 8][ks + tig + 4];
            }
#pragma unroll
            for (int ni = 0; ni < 4; ni++) {
                int cc = wn * 32 + ni * 8 + grp;
                bf[ni][0] = Bs[cc][ks + tig];
                bf[ni][1] = Bs[cc][ks + tig + 4];
            }
#pragma unroll
            for (int mi = 0; mi < 4; mi++)
#pragma unroll
                for (int ni = 0; ni < 4; ni++) mma_tf32(acc[mi][ni], a[mi], bf[ni]);
        }
        __syncthreads();
    }

    float lb = __ldg(lbias + l);
    size_t scoreBase = (size_t)bl * TT * TT;

#pragma unroll
    for (int mi = 0; mi < 4; mi++) {
#pragma unroll
        for (int h = 0; h < 2; h++) {
            int row = m0 + wm * 64 + mi * 16 + grp + h * 8;  // s
            bool ms = g_mask[b * TT + row] != 0.f;
#pragma unroll
            for (int ni = 0; ni < 4; ni++) {
                int col = n0 + wn * 32 + ni * 8 + tig * 2;  // e (even)
                float v0 = acc[mi][ni][h * 2 + 0] + lb;
                float v1 = acc[mi][ni][h * 2 + 1] + lb;
                size_t idx = scoreBase + (size_t)row * TT + col;
                float2 sv = make_float2(v0, v1);
                *(float2*)(out + idx) = sv;
                if (write_mask) {
                    bool me0 = g_mask[b * TT + col] != 0.f;
                    bool me1 = g_mask[b * TT + col + 1] != 0.f;
                    float q0 = (row <= col && ms && me0) ? 1.f : 0.f;
                    float q1 = (row <= col + 1 && ms && me1) ? 1.f : 0.f;
                    float2 qv = make_float2(q0, q1);
                    *(float2*)(out + maskoff + idx) = qv;
                }
            }
        }
    }
}

// ---------------- launch ----------------
extern "C" void kernel_launch(void* const* d_in, const int* in_sizes, int n_in,
                              void* d_out, int out_size) {
    const float* feat = (const float*)d_in[0];
    const void* mask_raw = d_in[1];
    const float* gamma = (const float*)d_in[2];
    const float* beta = (const float*)d_in[3];
    const float* ffw = (const float*)d_in[4];
    const float* ffb = (const float*)d_in[5];
    const float* lbias = (const float*)d_in[6];
    float* out = (float*)d_out;

    // Output layout: scores f32 [B,L,T,T] at offset 0; spans_mask (as f32)
    // appended if the buffer is large enough. Guard against smaller out_size
    // to avoid out-of-bounds writes.
    size_t osz = (size_t)out_size;
    int write_mask = (osz >= 2 * SCORE_ELEMS) ? 1 : 0;
    size_t maskoff = write_mask ? (osz - SCORE_ELEMS) : 0;

    maskprep_kernel<<<1, 256>>>(mask_raw);
    stats_kernel<<<128, 256>>>(feat);
    finalize_kernel<<<1, 256>>>(gamma, beta);
    gemm1_kernel<<<dim3(32, 32), 256>>>(feat, ffw, ffb);
    gemm2_kernel<<<dim3(4, 4, 128), 256>>>(lbias, out, maskoff, write_mask);
}

// round 17
// speedup vs baseline: 1.0752x; 1.0752x over previous
#include <cuda_runtime.h>
#include <cuda_bf16.h>
#include <cstdint>

// Problem constants (fixed by setup_inputs)
#define BB 8
#define TT 512
#define DD 768
#define LL 16
#define LD 128
#define NTOK 4096        // B*T
#define BN_EPS 1e-5f
#define SCORE_ELEMS ((size_t)BB * LL * TT * TT)   // 33554432

// ---------------- scratch (device globals: sanctioned, no runtime alloc) ----
__device__ float g_sums[2 * DD];
__device__ float g_scale[DD];
__device__ float g_shift[DD];
__device__ float g_mask[NTOK];                       // normalized 0/1
__device__ uint32_t g_afeat[(size_t)NTOK * DD];      // tf32 normalized feats
__device__ uint32_t g_bw[(size_t)4096 * DD];         // tf32 ff_w
__device__ uint32_t g_start[(size_t)BB * LL * TT * LD];  // tf32
__device__ uint32_t g_end  [(size_t)BB * LL * TT * LD];  // tf32

// ---------------- helpers ----------------
__device__ __forceinline__ uint32_t f2tf(float x) {
    uint32_t r;
    asm("cvt.rna.tf32.f32 %0, %1;" : "=r"(r) : "f"(x));
    return r;
}

__device__ __forceinline__ void mma_tf32(float* c, const uint32_t* a, const uint32_t* b) {
    asm volatile(
        "mma.sync.aligned.m16n8k8.row.col.f32.tf32.tf32.f32 "
        "{%0,%1,%2,%3},{%4,%5,%6,%7},{%8,%9},{%0,%1,%2,%3};"
        : "+f"(c[0]), "+f"(c[1]), "+f"(c[2]), "+f"(c[3])
        : "r"(a[0]), "r"(a[1]), "r"(a[2]), "r"(a[3]), "r"(b[0]), "r"(b[1]));
}

__device__ __forceinline__ uint32_t smem_u32(const void* p) {
    return (uint32_t)__cvta_generic_to_shared(p);
}
__device__ __forceinline__ void cp16(uint32_t dst, const void* src) {
    asm volatile("cp.async.cg.shared.global [%0], [%1], 16;" :: "r"(dst), "l"(src));
}
#define CP_COMMIT asm volatile("cp.async.commit_group;")
#define CP_WAIT0  asm volatile("cp.async.wait_group 0;")

// ---------------- kernel 0: mask dtype detect + normalize + zero stats ------
__global__ void maskprep_kernel(const void* __restrict__ mask_raw) {
    __shared__ int s_flags[2];
    __shared__ int s_hasfloat1;
    __shared__ int s_mode;
    int tid = threadIdx.x;  // 256
    if (tid == 0) { s_flags[0] = 0; s_flags[1] = 0; s_hasfloat1 = 0; }
    __syncthreads();

    const uint32_t* w = (const uint32_t*)mask_raw;
    int v01 = 0, vfl = 0, hf = 0;
    for (int i = tid; i < 1024; i += 256) {  // first 4KB only (safe all dtypes)
        uint32_t x = w[i];
        if (x > 1u) v01 = 1;
        if (x != 0u && x != 0x3F800000u) vfl = 1;
        if (x == 0x3F800000u) hf = 1;
    }
    if (v01) atomicOr(&s_flags[0], 1);
    if (vfl) atomicOr(&s_flags[1], 1);
    if (hf) atomicOr(&s_hasfloat1, 1);
    __syncthreads();
    if (tid == 0) {
        if (!s_flags[1] && s_hasfloat1) s_mode = 2;   // float32
        else if (!s_flags[0]) s_mode = 1;             // int32
        else s_mode = 0;                              // byte bool
    }
    __syncthreads();
    int mode = s_mode;
    for (int i = tid; i < NTOK; i += 256) {
        float m;
        if (mode == 0)      m = ((const unsigned char*)mask_raw)[i] ? 1.f : 0.f;
        else if (mode == 1) m = ((const int*)mask_raw)[i] ? 1.f : 0.f;
        else                m = (((const float*)mask_raw)[i] != 0.f) ? 1.f : 0.f;
        g_mask[i] = m;
    }
    for (int i = tid; i < 2 * DD; i += 256) g_sums[i] = 0.f;
}

// ---------------- kernel 1: masked BN partial sums ----------------
__global__ void stats_kernel(const float* __restrict__ feat) {
    int tid = threadIdx.x;
    int row0 = blockIdx.x * 32;
    float s[3] = {0.f, 0.f, 0.f}, q[3] = {0.f, 0.f, 0.f};
    for (int r = 0; r < 32; r++) {
        int row = row0 + r;
        if (g_mask[row] != 0.f) {
            const float* p = feat + (size_t)row * DD;
#pragma unroll
            for (int j = 0; j < 3; j++) {
                float x = p[tid + j * 256];
                s[j] += x;
                q[j] += x * x;
            }
        }
    }
#pragma unroll
    for (int j = 0; j < 3; j++) {
        atomicAdd(&g_sums[tid + j * 256], s[j]);
        atomicAdd(&g_sums[DD + tid + j * 256], q[j]);
    }
}

// ---------------- kernel 2: finalize -> scale/shift ----------------
__global__ void finalize_kernel(const float* __restrict__ gamma,
                                const float* __restrict__ beta) {
    __shared__ float ccnt;
    int tid = threadIdx.x;  // 256
    if (tid == 0) ccnt = 0.f;
    __syncthreads();
    float c = 0.f;
    for (int i = tid; i < NTOK; i += 256) c += g_mask[i];
#pragma unroll
    for (int off = 16; off; off >>= 1) c += __shfl_down_sync(0xffffffffu, c, off);
    if ((tid & 31) == 0) atomicAdd(&ccnt, c);
    __syncthreads();
    float denom = fmaxf(ccnt, 1.f);
    for (int d = tid; d < DD; d += 256) {
        float mean = g_sums[d] / denom;
        float var = fmaxf(g_sums[DD + d] / denom - mean * mean, 0.f);
        float sc = rsqrtf(var + BN_EPS) * gamma[d];
        g_scale[d] = sc;
        g_shift[d] = beta[d] - mean * sc;
    }
}

// ---------------- kernel 2.5: pre-transform to tf32 scratch -----------------
// y=0: g_afeat = tf32((feat*scale+shift)*mask); y=1: g_bw = tf32(ffw)
__global__ void prep_kernel(const float* __restrict__ feat,
                            const float* __restrict__ ffw) {
    int i = blockIdx.x * 256 + threadIdx.x;   // float4 group, 786432 per matrix
    int row = i / (DD / 4);
    int col = (i % (DD / 4)) * 4;
    size_t off = (size_t)row * DD + col;
    if (blockIdx.y == 0) {
        float4 x = *(const float4*)(feat + off);
        float4 sc = *(const float4*)(g_scale + col);
        float4 sh = *(const float4*)(g_shift + col);
        float m = g_mask[row];
        uint4 v;
        v.x = f2tf(fmaf(x.x, sc.x, sh.x) * m);
        v.y = f2tf(fmaf(x.y, sc.y, sh.y) * m);
        v.z = f2tf(fmaf(x.z, sc.z, sh.z) * m);
        v.w = f2tf(fmaf(x.w, sc.w, sh.w) * m);
        *(uint4*)(g_afeat + off) = v;
    } else {
        float4 x = *(const float4*)(ffw + off);
        uint4 v;
        v.x = f2tf(x.x); v.y = f2tf(x.y); v.z = f2tf(x.z); v.w = f2tf(x.w);
        *(uint4*)(g_bw + off) = v;
    }
}

// ---------------- kernel 3: GEMM1 (cp.async double-buffered) ----------------
// C tile 128x128, K-step 32, 8 warps (2m x 4n), warp tile 64x32, tf32 MMA.
// Dyn smem: As[2][128][36] + Bs[2][128][36] u32 = 73728 B.
__global__ __launch_bounds__(256, 2)
void gemm1_kernel(const float* __restrict__ ffb) {
    extern __shared__ uint32_t sh[];
    uint32_t (*As)[36] = (uint32_t(*)[36])sh;            // [2*128][36]
    uint32_t (*Bs)[36] = (uint32_t(*)[36])(sh + 2 * 128 * 36);

    int tid = threadIdx.x;
    int m0 = blockIdx.y * 128, n0 = blockIdx.x * 128;
    int warp = tid >> 5, lane = tid & 31;
    int wm = warp >> 2, wn = warp & 3;
    int grp = lane >> 2, tig = lane & 3;

    float acc[4][4][4];
#pragma unroll
    for (int i = 0; i < 4; i++)
#pragma unroll
        for (int j = 0; j < 4; j++)
#pragma unroll
            for (int k = 0; k < 4; k++) acc[i][j][k] = 0.f;

    int ldRow = tid >> 3;        // 0..31
    int ldK = (tid & 7) * 4;     // 0..28
    const uint32_t* Ag = g_afeat + (size_t)m0 * DD;
    const uint32_t* Bg = g_bw + (size_t)n0 * DD;
    uint32_t aBase = smem_u32(&As[0][0]);
    uint32_t bBase = smem_u32(&Bs[0][0]);

#define G1_ISSUE(k0, buf)                                                      \
    {                                                                          \
        _Pragma("unroll")                                                      \
        for (int p = 0; p < 4; p++) {                                          \
            int r = ldRow + p * 32;                                            \
            cp16(aBase + (((buf) * 128 + r) * 36 + ldK) * 4,                   \
                 Ag + (size_t)r * DD + (k0) + ldK);                            \
            cp16(bBase + (((buf) * 128 + r) * 36 + ldK) * 4,                   \
                 Bg + (size_t)r * DD + (k0) + ldK);                            \
        }                                                                      \
        CP_COMMIT;                                                             \
    }

    G1_ISSUE(0, 0);
    const int NCH = DD / 32;  // 24
    for (int c = 0; c < NCH; c++) {
        int buf = c & 1;
        CP_WAIT0;
        __syncthreads();
        if (c + 1 < NCH) G1_ISSUE((c + 1) * 32, buf ^ 1);

#pragma unroll
        for (int kk = 0; kk < 4; kk++) {
            int ks = kk * 8;
            uint32_t a[4][4], b[4][2];
#pragma unroll
            for (int mi = 0; mi < 4; mi++) {
                int r = buf * 128 + wm * 64 + mi * 16;
                a[mi][0] = As[r + grp][ks + tig];
                a[mi][1] = As[r + grp + 8][ks + tig];
                a[mi][2] = As[r + grp][ks + tig + 4];
                a[mi][3] = As[r + grp + 8][ks + tig + 4];
            }
#pragma unroll
            for (int ni = 0; ni < 4; ni++) {
                int cc = buf * 128 + wn * 32 + ni * 8 + grp;
                b[ni][0] = Bs[cc][ks + tig];
                b[ni][1] = Bs[cc][ks + tig + 4];
            }
#pragma unroll
            for (int mi = 0; mi < 4; mi++)
#pragma unroll
                for (int ni = 0; ni < 4; ni++) mma_tf32(acc[mi][ni], a[mi], b[ni]);
        }
    }
#undef G1_ISSUE

    // epilogue: bias + relu + permute into start/end (stored as tf32 bits)
#pragma unroll
    for (int ni = 0; ni < 4; ni++) {
        int col = n0 + wn * 32 + ni * 8 + tig * 2;  // even
        float b0 = __ldg(ffb + col), b1 = __ldg(ffb + col + 1);
        int l = col >> 8;
        int d2 = (col & 255) >> 1;
#pragma unroll
        for (int mi = 0; mi < 4; mi++) {
#pragma unroll
            for (int h = 0; h < 2; h++) {
                int row = m0 + wm * 64 + mi * 16 + grp + h * 8;
                float h0 = fmaxf(acc[mi][ni][h * 2 + 0] + b0, 0.f);
                float h1 = fmaxf(acc[mi][ni][h * 2 + 1] + b1, 0.f);
                int bb = row >> 9, s = row & 511;
                size_t idx = ((size_t)((bb * LL + l) * TT + s)) * LD + d2;
                g_start[idx] = f2tf(h0);
                g_end[idx] = f2tf(h1);
            }
        }
    }
}

// ---------------- kernel 4: GEMM2 (cp.async double-buffered) ----------------
__global__ __launch_bounds__(256, 2)
void gemm2_kernel(const float* __restrict__ lbias,
                  float* __restrict__ out,
                  size_t maskoff,
                  int write_mask) {
    extern __shared__ uint32_t sh[];
    uint32_t (*As)[36] = (uint32_t(*)[36])sh;
    uint32_t (*Bs)[36] = (uint32_t(*)[36])(sh + 2 * 128 * 36);

    int tid = threadIdx.x;
    int bl = blockIdx.z;
    int b = bl >> 4, l = bl & 15;
    int m0 = blockIdx.y * 128, n0 = blockIdx.x * 128;
    int warp = tid >> 5, lane = tid & 31;
    int wm = warp >> 2, wn = warp & 3;
    int grp = lane >> 2, tig = lane & 3;

    const uint32_t* S = g_start + (size_t)bl * TT * LD + (size_t)m0 * LD;
    const uint32_t* E = g_end + (size_t)bl * TT * LD + (size_t)n0 * LD;

    float acc[4][4][4];
#pragma unroll
    for (int i = 0; i < 4; i++)
#pragma unroll
        for (int j = 0; j < 4; j++)
#pragma unroll
            for (int k = 0; k < 4; k++) acc[i][j][k] = 0.f;

    int ldRow = tid >> 3;
    int ldK = (tid & 7) * 4;
    uint32_t aBase = smem_u32(&As[0][0]);
    uint32_t bBase = smem_u32(&Bs[0][0]);

#define G2_ISSUE(k0, buf)                                                      \
    {                                                                          \
        _Pragma("unroll")                                                      \
        for (int p = 0; p < 4; p++) {                                          \
            int r = ldRow + p * 32;                                            \
            cp16(aBase + (((buf) * 128 + r) * 36 + ldK) * 4,                   \
                 S + (size_t)r * LD + (k0) + ldK);                             \
            cp16(bBase + (((buf) * 128 + r) * 36 + ldK) * 4,                   \
                 E + (size_t)r * LD + (k0) + ldK);                             \
        }                                                                      \
        CP_COMMIT;                                                             \
    }

    G2_ISSUE(0, 0);
    const int NCH = LD / 32;  // 4
    for (int c = 0; c < NCH; c++) {
        int buf = c & 1;
        CP_WAIT0;
        __syncthreads();
        if (c + 1 < NCH) G2_ISSUE((c + 1) * 32, buf ^ 1);

#pragma unroll
        for (int kk = 0; kk < 4; kk++) {
            int ks = kk * 8;
            uint32_t a[4][4], bf[4][2];
#pragma unroll
            for (int mi = 0; mi < 4; mi++) {
                int r = buf * 128 + wm * 64 + mi * 16;
                a[mi][0] = As[r + grp][ks + tig];
                a[mi][1] = As[r + grp + 8][ks + tig];
                a[mi][2] = As[r + grp][ks + tig + 4];
                a[mi][3] = As[r + grp + 8][ks + tig + 4];
            }
#pragma unroll
            for (int ni = 0; ni < 4; ni++) {
                int cc = buf * 128 + wn * 32 + ni * 8 + grp;
                bf[ni][0] = Bs[cc][ks + tig];
                bf[ni][1] = Bs[cc][ks + tig + 4];
            }
#pragma unroll
            for (int mi = 0; mi < 4; mi++)
#pragma unroll
                for (int ni = 0; ni < 4; ni++) mma_tf32(acc[mi][ni], a[mi], bf[ni]);
        }
    }
#undef G2_ISSUE

    float lb = __ldg(lbias + l);
    size_t scoreBase = (size_t)bl * TT * TT;

#pragma unroll
    for (int mi = 0; mi < 4; mi++) {
#pragma unroll
        for (int h = 0; h < 2; h++) {
            int row = m0 + wm * 64 + mi * 16 + grp + h * 8;  // s
            bool ms = g_mask[b * TT + row] != 0.f;
#pragma unroll
            for (int ni = 0; ni < 4; ni++) {
                int col = n0 + wn * 32 + ni * 8 + tig * 2;  // e (even)
                float v0 = acc[mi][ni][h * 2 + 0] + lb;
                float v1 = acc[mi][ni][h * 2 + 1] + lb;
                size_t idx = scoreBase + (size_t)row * TT + col;
                *(float2*)(out + idx) = make_float2(v0, v1);
                if (write_mask) {
                    bool me0 = g_mask[b * TT + col] != 0.f;
                    bool me1 = g_mask[b * TT + col + 1] != 0.f;
                    float q0 = (row <= col && ms && me0) ? 1.f : 0.f;
                    float q1 = (row <= col + 1 && ms && me1) ? 1.f : 0.f;
                    *(float2*)(out + maskoff + idx) = make_float2(q0, q1);
                }
            }
        }
    }
}

// ---------------- launch ----------------
extern "C" void kernel_launch(void* const* d_in, const int* in_sizes, int n_in,
                              void* d_out, int out_size) {
    const float* feat = (const float*)d_in[0];
    const void* mask_raw = d_in[1];
    const float* gamma = (const float*)d_in[2];
    const float* beta = (const float*)d_in[3];
    const float* ffw = (const float*)d_in[4];
    const float* ffb = (const float*)d_in[5];
    const float* lbias = (const float*)d_in[6];
    float* out = (float*)d_out;

    size_t osz = (size_t)out_size;
    int write_mask = (osz >= 2 * SCORE_ELEMS) ? 1 : 0;
    size_t maskoff = write_mask ? (osz - SCORE_ELEMS) : 0;

    const int DSMEM = 2 * 2 * 128 * 36 * 4;  // 73728 B
    static int attr_done = 0;
    if (!attr_done) {
        cudaFuncSetAttribute(gemm1_kernel, cudaFuncAttributeMaxDynamicSharedMemorySize, DSMEM);
        cudaFuncSetAttribute(gemm2_kernel, cudaFuncAttributeMaxDynamicSharedMemorySize, DSMEM);
        attr_done = 1;
    }

    maskprep_kernel<<<1, 256>>>(mask_raw);
    stats_kernel<<<128, 256>>>(feat);
    finalize_kernel<<<1, 256>>>(gamma, beta);
    prep_kernel<<<dim3(NTOK * DD / 4 / 256, 2), 256>>>(feat, ffw);
    gemm1_kernel<<<dim3(32, 32), 256, DSMEM>>>(ffb);
    gemm2_kernel<<<dim3(4, 4, 128), 256, DSMEM>>>(lbias, out, maskoff, write_mask);
}